// round 15
// baseline (speedup 1.0000x reference)
#include <cuda_runtime.h>
#include <cuda_fp16.h>
#include <cstdint>
#include <math.h>

#define HIDDEN   4096
#define NKV      8
#define NH       32
#define HD       128
#define BATCH    2
#define SEQ      2048
#define TOKENS   (BATCH*SEQ)   // 4096
#define KVDIM    (NKV*HD)      // 1024

// ---------------- scratch (device globals; no runtime allocation) ----------
__device__ __half g_xh [TOKENS*HIDDEN];
__device__ __half g_wqh[HIDDEN*HIDDEN];
__device__ __half g_wkh[KVDIM*HIDDEN];
__device__ __half g_wvh[KVDIM*HIDDEN];
__device__ __half g_woh[HIDDEN*HIDDEN];
__device__ __half g_qh [TOKENS*HIDDEN];
__device__ __half g_kh [TOKENS*KVDIM];
__device__ __half g_vh [TOKENS*KVDIM];
__device__ __half g_vth[TOKENS*KVDIM];                    // [B][KVDIM][SEQ]
__device__ __half g_aoh[TOKENS*HIDDEN];

// ======================= helpers ============================================
__device__ __forceinline__ uint32_t smem_u32(const void* p) {
    uint32_t a;
    asm("{ .reg .u64 t; cvta.to.shared.u64 t, %1; cvt.u32.u64 %0, t; }"
        : "=r"(a) : "l"(p));
    return a;
}
__device__ __forceinline__ void cp16(uint32_t dst, const void* src) {
    asm volatile("cp.async.cg.shared.global [%0], [%1], 16;" :: "r"(dst), "l"(src));
}
__device__ __forceinline__ void cp_commit() { asm volatile("cp.async.commit_group;" ::: "memory"); }
template<int N> __device__ __forceinline__ void cp_wait() {
    asm volatile("cp.async.wait_group %0;" :: "n"(N) : "memory");
}
__device__ __forceinline__ void ldm_x4(uint32_t* r, uint32_t addr) {
    asm volatile("ldmatrix.sync.aligned.m8n8.x4.shared.b16 {%0,%1,%2,%3}, [%4];"
        : "=r"(r[0]), "=r"(r[1]), "=r"(r[2]), "=r"(r[3]) : "r"(addr));
}
__device__ __forceinline__ void mma16816(float* d, const uint32_t* a,
                                         uint32_t b0, uint32_t b1) {
    asm volatile(
        "mma.sync.aligned.m16n8k16.row.col.f32.f16.f16.f32 "
        "{%0,%1,%2,%3}, {%4,%5,%6,%7}, {%8,%9}, {%0,%1,%2,%3};"
        : "+f"(d[0]), "+f"(d[1]), "+f"(d[2]), "+f"(d[3])
        : "r"(a[0]), "r"(a[1]), "r"(a[2]), "r"(a[3]), "r"(b0), "r"(b1));
}
__device__ __forceinline__ uint32_t pack_h2(__half a, __half b) {
    __half2 h = __halves2half2(a, b);
    return *(uint32_t*)&h;
}

// ======================= fp32 -> fp16 conversion (all tensors, one launch) ==
#define XN4 (TOKENS*HIDDEN/4)
#define WN4 (HIDDEN*HIDDEN/4)
#define KN4 (KVDIM*HIDDEN/4)
#define CVT_TOT (XN4 + 2*WN4 + 2*KN4)
__global__ __launch_bounds__(256) void split_all(
    const float4* __restrict__ x,
    const float4* __restrict__ wq, const float4* __restrict__ wk,
    const float4* __restrict__ wv, const float4* __restrict__ wo,
    __half2* __restrict__ xo,
    __half2* __restrict__ qo, __half2* __restrict__ ko,
    __half2* __restrict__ vo, __half2* __restrict__ oo)
{
    int i = blockIdx.x * blockDim.x + threadIdx.x;
    const float4* src;
    __half2* dst;
    int idx;
    if (i < XN4)                          { src = x;  dst = xo; idx = i; }
    else if (i < XN4 + WN4)               { src = wq; dst = qo; idx = i - XN4; }
    else if (i < XN4 + WN4 + KN4)         { src = wk; dst = ko; idx = i - XN4 - WN4; }
    else if (i < XN4 + WN4 + 2 * KN4)     { src = wv; dst = vo; idx = i - XN4 - WN4 - KN4; }
    else if (i < CVT_TOT)                 { src = wo; dst = oo; idx = i - XN4 - WN4 - 2 * KN4; }
    else return;
    float4 v = src[idx];
    dst[2 * idx]     = __halves2half2(__float2half_rn(v.x), __float2half_rn(v.y));
    dst[2 * idx + 1] = __halves2half2(__float2half_rn(v.z), __float2half_rn(v.w));
}

// ======================= QKV GEMM (single-term, hi out) =====================
#define BM 128
#define BN 256
#define BK 64
#define ROWB 144
#define A_ST (BM*ROWB)                 // 18432
#define B_ST (BN*ROWB)                 // 36864
#define STAGE_B (A_ST + B_ST)          // 55296
#define NSTAGE 3
#define GEMM_SMEM (NSTAGE*STAGE_B)     // 165888

// swizzled block mapping (supertiles of 8 m-blocks)
__device__ __forceinline__ void cta_map(int gx, int gy, int& mb, int& nb) {
    int lin = blockIdx.y * gx + blockIdx.x;
    const int SW = 8;
    int per  = SW * gx;
    int band = lin / per;
    int rem  = lin - band * per;
    int h    = gy - band * SW; if (h > SW) h = SW;
    mb = band * SW + rem % h;
    nb = rem / h;
}

__global__ __launch_bounds__(256, 1) void qkv_hmma(
    const __half* __restrict__ xh,
    const __half* __restrict__ wqh,
    const __half* __restrict__ wkh,
    const __half* __restrict__ wvh,
    __half* __restrict__ qh,
    __half* __restrict__ kh,
    __half* __restrict__ vh)
{
    extern __shared__ char smraw[];
    const uint32_t sbase = smem_u32(smraw);
    const int tid  = threadIdx.x;
    const int wid  = tid >> 5;
    const int lane = tid & 31;
    const int wm   = wid & 1;
    const int wn   = wid >> 1;

    int mb, nb;
    cta_map(gridDim.x, gridDim.y, mb, nb);
    const int m0 = mb * BM;

    const __half* Bh_;
    __half* Ch;
    int Nout, ncol;
    if (nb < 16)      { Bh_ = wqh; Ch = qh; Nout = HIDDEN; ncol = nb * BN; }
    else if (nb < 20) { Bh_ = wkh; Ch = kh; Nout = KVDIM;  ncol = (nb - 16) * BN; }
    else              { Bh_ = wvh; Ch = vh; Nout = KVDIM;  ncol = (nb - 20) * BN; }

    const __half* A0h = xh + (size_t)m0 * HIDDEN;
    const __half* B0h = Bh_ + (size_t)ncol * HIDDEN;
    const int K = HIDDEN;

    auto bA = [&](int s) { return sbase + s * STAGE_B; };
    auto bB = [&](int s) { return sbase + s * STAGE_B + A_ST; };

    auto load_stage = [&](int s, int k0) {
#pragma unroll
        for (int t = 0; t < 4; t++) {
            int idx = tid + t * 256;
            int r = idx >> 3, c = idx & 7;
            uint32_t d = (uint32_t)(r * ROWB + c * 16);
            cp16(bA(s) + d, A0h + (size_t)r * K + k0 + c * 8);
        }
#pragma unroll
        for (int t = 0; t < 8; t++) {
            int idx = tid + t * 256;
            int r = idx >> 3, c = idx & 7;
            uint32_t d = (uint32_t)(r * ROWB + c * 16);
            cp16(bB(s) + d, B0h + (size_t)r * K + k0 + c * 8);
        }
    };

    float acc[4][8][4];
#pragma unroll
    for (int i = 0; i < 4; i++)
#pragma unroll
        for (int j = 0; j < 8; j++)
#pragma unroll
            for (int t = 0; t < 4; t++) acc[i][j][t] = 0.f;

    const int aRow = lane & 15;
    const int aKof = (lane >> 4) * 16;
    const int bRow = (lane & 7) + ((lane & 16) ? 8 : 0);
    const int bKof = (lane & 8) ? 16 : 0;
    const int warpM = wm * 64;
    const int warpN = wn * 64;

    const int nst = K / BK;
    load_stage(0, 0);
    cp_commit();
    load_stage(1, BK);
    cp_commit();

    for (int s = 0; s < nst; s++) {
        const int buf = s % NSTAGE;
        if (s + 1 < nst) cp_wait<1>(); else cp_wait<0>();
        __syncthreads();

        const uint32_t sA = bA(buf), sB = bB(buf);

#pragma unroll
        for (int ks = 0; ks < 4; ks++) {
            const int kb = ks * 32;
            uint32_t ah[4][4], bh[4][4];
#pragma unroll
            for (int mi = 0; mi < 4; mi++) {
                uint32_t ad = (uint32_t)((warpM + mi * 16 + aRow) * ROWB + kb + aKof);
                ldm_x4(ah[mi], sA + ad);
            }
#pragma unroll
            for (int np = 0; np < 4; np++) {
                uint32_t bd = (uint32_t)((warpN + np * 16 + bRow) * ROWB + kb + bKof);
                ldm_x4(bh[np], sB + bd);
            }
#pragma unroll
            for (int np = 0; np < 4; np++)
#pragma unroll
                for (int q = 0; q < 2; q++) {
                    const int ni = np * 2 + q;
                    const uint32_t b0 = bh[np][q * 2], b1 = bh[np][q * 2 + 1];
#pragma unroll
                    for (int mi = 0; mi < 4; mi++)
                        mma16816(acc[mi][ni], ah[mi], b0, b1);
                }
        }

        if (s + 2 < nst) {
            load_stage((s + 2) % NSTAGE, (s + 2) * BK);
            cp_commit();
        }
    }

    const int er = lane >> 2;
    const int ec = (lane & 3) * 2;
#pragma unroll
    for (int mi = 0; mi < 4; mi++)
#pragma unroll
        for (int ni = 0; ni < 8; ni++) {
            size_t off0 = (size_t)(m0 + warpM + mi * 16 + er) * Nout
                        + (ncol + warpN + ni * 8 + ec);
            size_t off1 = off0 + (size_t)8 * Nout;
            *(uint32_t*)(Ch + off0) = pack_h2(
                __float2half_rn(acc[mi][ni][0]), __float2half_rn(acc[mi][ni][1]));
            *(uint32_t*)(Ch + off1) = pack_h2(
                __float2half_rn(acc[mi][ni][2]), __float2half_rn(acc[mi][ni][3]));
        }
}

// ======================= Wo GEMM (single-term, 256x128 tile) ================
#define WOM 256
#define WON 128
#define WO_A_ST (WOM*ROWB)             // 36864
#define WO_B_ST (WON*ROWB)             // 18432
#define WO_STAGE (WO_A_ST + WO_B_ST)   // 55296
#define WO_SMEM (NSTAGE*WO_STAGE)      // 165888

__global__ __launch_bounds__(256, 1) void gemm_wo(
    const __half* __restrict__ Ah, const __half* __restrict__ Bh,
    float* __restrict__ C, int N, int K)
{
    extern __shared__ char smraw[];
    const uint32_t sbase = smem_u32(smraw);
    const int tid  = threadIdx.x;
    const int wid  = tid >> 5;
    const int lane = tid & 31;
    const int wm   = wid & 3;
    const int wn   = wid >> 2;

    int mb, nb;
    cta_map(gridDim.x, gridDim.y, mb, nb);
    const int m0 = mb * WOM, n0 = nb * WON;

    const __half* A0 = Ah + (size_t)m0 * K;
    const __half* B0 = Bh + (size_t)n0 * K;

    auto bA = [&](int s) { return sbase + s * WO_STAGE; };
    auto bB = [&](int s) { return sbase + s * WO_STAGE + WO_A_ST; };

    auto load_stage = [&](int s, int k0) {
#pragma unroll
        for (int t = 0; t < 8; t++) {
            int idx = tid + t * 256;
            int r = idx >> 3, c = idx & 7;
            uint32_t d = (uint32_t)(r * ROWB + c * 16);
            cp16(bA(s) + d, A0 + (size_t)r * K + k0 + c * 8);
        }
#pragma unroll
        for (int t = 0; t < 4; t++) {
            int idx = tid + t * 256;
            int r = idx >> 3, c = idx & 7;
            uint32_t d = (uint32_t)(r * ROWB + c * 16);
            cp16(bB(s) + d, B0 + (size_t)r * K + k0 + c * 8);
        }
    };

    float acc[4][8][4];
#pragma unroll
    for (int i = 0; i < 4; i++)
#pragma unroll
        for (int j = 0; j < 8; j++)
#pragma unroll
            for (int t = 0; t < 4; t++) acc[i][j][t] = 0.f;

    const int aRow = lane & 15;
    const int aKof = (lane >> 4) * 16;
    const int bRow = (lane & 7) + ((lane & 16) ? 8 : 0);
    const int bKof = (lane & 8) ? 16 : 0;
    const int warpM = wm * 64;
    const int warpN = wn * 64;

    const int nst = K / BK;
    load_stage(0, 0);
    cp_commit();
    load_stage(1, BK);
    cp_commit();

    for (int s = 0; s < nst; s++) {
        const int buf = s % NSTAGE;
        if (s + 1 < nst) cp_wait<1>(); else cp_wait<0>();
        __syncthreads();

        const uint32_t sA = bA(buf), sB = bB(buf);

#pragma unroll
        for (int ks = 0; ks < 4; ks++) {
            const int kb = ks * 32;
            uint32_t ah[4][4], bh[4][4];
#pragma unroll
            for (int mi = 0; mi < 4; mi++) {
                uint32_t ad = (uint32_t)((warpM + mi * 16 + aRow) * ROWB + kb + aKof);
                ldm_x4(ah[mi], sA + ad);
            }
#pragma unroll
            for (int np = 0; np < 4; np++) {
                uint32_t bd = (uint32_t)((warpN + np * 16 + bRow) * ROWB + kb + bKof);
                ldm_x4(bh[np], sB + bd);
            }
#pragma unroll
            for (int np = 0; np < 4; np++)
#pragma unroll
                for (int q = 0; q < 2; q++) {
                    const int ni = np * 2 + q;
                    const uint32_t b0 = bh[np][q * 2], b1 = bh[np][q * 2 + 1];
#pragma unroll
                    for (int mi = 0; mi < 4; mi++)
                        mma16816(acc[mi][ni], ah[mi], b0, b1);
                }
        }

        if (s + 2 < nst) {
            load_stage((s + 2) % NSTAGE, (s + 2) * BK);
            cp_commit();
        }
    }

    const int er = lane >> 2;
    const int ec = (lane & 3) * 2;
#pragma unroll
    for (int mi = 0; mi < 4; mi++)
#pragma unroll
        for (int ni = 0; ni < 8; ni++) {
            float* p = C + (size_t)(m0 + warpM + mi * 16 + er) * N
                         + (n0 + warpN + ni * 8 + ec);
            p[0] = acc[mi][ni][0];
            p[1] = acc[mi][ni][1];
            float* q = p + (size_t)8 * N;
            q[0] = acc[mi][ni][2];
            q[1] = acc[mi][ni][3];
        }
}

// ======================= V transpose (hi only) ==============================
__global__ __launch_bounds__(256) void transpose_v(
    const __half* __restrict__ vh, __half* __restrict__ vth)
{
    __shared__ __half th[32][33];
    const int b  = blockIdx.z;
    const int k0 = blockIdx.y * 32;
    const int s0 = blockIdx.x * 32;
    const int tx = threadIdx.x & 31;
    const int ty = threadIdx.x >> 5;
#pragma unroll
    for (int i = 0; i < 4; i++) {
        int row = ty + i * 8;
        th[row][tx] = vh[(size_t)(b * SEQ + s0 + row) * KVDIM + k0 + tx];
    }
    __syncthreads();
#pragma unroll
    for (int i = 0; i < 4; i++) {
        int row = ty + i * 8;
        vth[((size_t)b * KVDIM + k0 + row) * SEQ + s0 + tx] = th[tx][row];
    }
}

// ======================= HMMA flash attention ================================
// 64 q-rows/CTA, 128 threads (4 warps), 64-col kv blocks, 2 CTAs/SM.
// QK: Qh*Kh.  PV: Ph*Vh.  Softmax in log2 domain.
#define QROWB 272
#define KROWB 272
#define VROWB 144
#define FQ_B     (64*QROWB)            // 17408
#define K_TILE_B (64*KROWB)            // 17408
#define V_TILE_B (128*VROWB)           // 18432
#define SKV_BASE FQ_B
#define SKV_STRIDE (K_TILE_B + V_TILE_B)  // 35840
#define OFF_KH 0
#define OFF_VTH K_TILE_B
#define FLASH_SMEM (SKV_BASE + 2*SKV_STRIDE)   // 89088

__global__ __launch_bounds__(128, 2) void flash_hmma(
    const __half* __restrict__ qh,
    const __half* __restrict__ kh,
    const __half* __restrict__ vth,
    __half* __restrict__ aoh)
{
    extern __shared__ char smraw[];
    const uint32_t sb = smem_u32(smraw);
    const int tid = threadIdx.x, wid = tid >> 5, lane = tid & 31;
    const int qb = (int)(gridDim.x - 1 - blockIdx.x);   // big work first
    const int hq = blockIdx.y, b = blockIdx.z;
    const int kvh = hq >> 2;
    const int qrow0 = qb * 64;
    const int g = lane >> 2, tig = lane & 3;
    const float cs = 0.08838834764831845f * 1.4426950408889634f;

    const __half* qhg = qh + (size_t)(b * SEQ + qrow0) * HIDDEN + hq * HD;
#pragma unroll
    for (int t = 0; t < 8; t++) {
        int idx = tid + t * 128;
        int r = idx >> 4, c = idx & 15;
        cp16(sb + (uint32_t)(r * QROWB + c * 16), qhg + (size_t)r * HIDDEN + c * 8);
    }
    cp_commit();

    const __half* khg = kh + (size_t)(b * SEQ) * KVDIM + kvh * HD;
    const __half* vthg = vth + ((size_t)b * KVDIM + kvh * HD) * SEQ;

    auto load_kv = [&](int stage, int j) {
        uint32_t base = sb + SKV_BASE + stage * SKV_STRIDE;
        int c0 = j * 64;
#pragma unroll
        for (int t = 0; t < 8; t++) {                 // K: 64 rows x 16 chunks
            int idx = tid + t * 128;
            int r = idx >> 4, c = idx & 15;
            uint32_t d = (uint32_t)(r * KROWB + c * 16);
            cp16(base + OFF_KH + d, khg + (size_t)(c0 + r) * KVDIM + c * 8);
        }
#pragma unroll
        for (int t = 0; t < 8; t++) {                 // V^T: 128 rows x 8 chunks
            int idx = tid + t * 128;
            int r = idx >> 3, c = idx & 7;
            uint32_t d = (uint32_t)(r * VROWB + c * 16);
            cp16(base + OFF_VTH + d, vthg + (size_t)r * SEQ + c0 + c * 8);
        }
    };

    const int nb = qb + 1;
    load_kv(0, 0);
    cp_commit();

    float oacc[16][4];
#pragma unroll
    for (int i = 0; i < 16; i++)
#pragma unroll
        for (int t = 0; t < 4; t++) oacc[i][t] = 0.f;
    float m0 = -1e30f, m1 = -1e30f, l0 = 0.f, l1 = 0.f;

    const int aRow = lane & 15;
    const int aKof = (lane >> 4) * 16;
    const int bRow = (lane & 7) + ((lane & 16) ? 8 : 0);
    const int bKof = (lane & 8) ? 16 : 0;

    const int rg0 = qrow0 + 16 * wid + g;
    const int rg1 = rg0 + 8;

    for (int j = 0; j < nb; j++) {
        const int buf = j & 1;
        if (j + 1 < nb) {
            load_kv(1 - buf, j + 1);
            cp_commit();
            cp_wait<1>();
        } else {
            cp_wait<0>();
        }
        __syncthreads();

        const uint32_t kbase = sb + SKV_BASE + buf * SKV_STRIDE;

        float sacc[8][4];
#pragma unroll
        for (int i = 0; i < 8; i++)
#pragma unroll
            for (int t = 0; t < 4; t++) sacc[i][t] = 0.f;

#pragma unroll
        for (int kd = 0; kd < 8; kd++) {
            uint32_t aa = (uint32_t)((16 * wid + aRow) * QROWB + kd * 32 + aKof);
            uint32_t ah[4];
            ldm_x4(ah, sb + aa);
#pragma unroll
            for (int np = 0; np < 4; np++) {
                uint32_t ba = (uint32_t)((np * 16 + bRow) * KROWB + kd * 32 + bKof);
                uint32_t bh[4];
                ldm_x4(bh, kbase + OFF_KH + ba);
                mma16816(sacc[np * 2],     ah, bh[0], bh[1]);
                mma16816(sacc[np * 2 + 1], ah, bh[2], bh[3]);
            }
        }

        const int c0 = j * 64;
        if (j == qb) {
#pragma unroll
            for (int ni = 0; ni < 8; ni++) {
                int cg = c0 + ni * 8 + 2 * tig;
                if (cg     > rg0) sacc[ni][0] = -1e30f;
                if (cg + 1 > rg0) sacc[ni][1] = -1e30f;
                if (cg     > rg1) sacc[ni][2] = -1e30f;
                if (cg + 1 > rg1) sacc[ni][3] = -1e30f;
            }
        }

        float vm0 = -1e30f, vm1 = -1e30f;
#pragma unroll
        for (int ni = 0; ni < 8; ni++) {
            vm0 = fmaxf(vm0, fmaxf(sacc[ni][0], sacc[ni][1]));
            vm1 = fmaxf(vm1, fmaxf(sacc[ni][2], sacc[ni][3]));
        }
        vm0 = fmaxf(vm0, __shfl_xor_sync(0xffffffffu, vm0, 1));
        vm0 = fmaxf(vm0, __shfl_xor_sync(0xffffffffu, vm0, 2));
        vm1 = fmaxf(vm1, __shfl_xor_sync(0xffffffffu, vm1, 1));
        vm1 = fmaxf(vm1, __shfl_xor_sync(0xffffffffu, vm1, 2));
        float mn0 = fmaxf(m0, vm0 * cs), mn1 = fmaxf(m1, vm1 * cs);
        float al0 = exp2f(m0 - mn0), al1 = exp2f(m1 - mn1);
        float sum0 = 0.f, sum1 = 0.f;
#pragma unroll
        for (int ni = 0; ni < 8; ni++) {
            sacc[ni][0] = exp2f(fmaf(sacc[ni][0], cs, -mn0));
            sacc[ni][1] = exp2f(fmaf(sacc[ni][1], cs, -mn0));
            sacc[ni][2] = exp2f(fmaf(sacc[ni][2], cs, -mn1));
            sacc[ni][3] = exp2f(fmaf(sacc[ni][3], cs, -mn1));
            sum0 += sacc[ni][0] + sacc[ni][1];
            sum1 += sacc[ni][2] + sacc[ni][3];
        }
        sum0 += __shfl_xor_sync(0xffffffffu, sum0, 1);
        sum0 += __shfl_xor_sync(0xffffffffu, sum0, 2);
        sum1 += __shfl_xor_sync(0xffffffffu, sum1, 1);
        sum1 += __shfl_xor_sync(0xffffffffu, sum1, 2);
        l0 = l0 * al0 + sum0;  l1 = l1 * al1 + sum1;
        m0 = mn0;  m1 = mn1;

#pragma unroll
        for (int nd = 0; nd < 16; nd++) {
            oacc[nd][0] *= al0;  oacc[nd][1] *= al0;
            oacc[nd][2] *= al1;  oacc[nd][3] *= al1;
        }

        uint32_t pah[4][4];
#pragma unroll
        for (int t = 0; t < 4; t++) {
            pah[t][0] = pack_h2(__float2half_rn(sacc[2 * t][0]),
                                __float2half_rn(sacc[2 * t][1]));
            pah[t][1] = pack_h2(__float2half_rn(sacc[2 * t][2]),
                                __float2half_rn(sacc[2 * t][3]));
            pah[t][2] = pack_h2(__float2half_rn(sacc[2 * t + 1][0]),
                                __float2half_rn(sacc[2 * t + 1][1]));
            pah[t][3] = pack_h2(__float2half_rn(sacc[2 * t + 1][2]),
                                __float2half_rn(sacc[2 * t + 1][3]));
        }

#pragma unroll
        for (int t = 0; t < 4; t++) {
#pragma unroll
            for (int np = 0; np < 8; np++) {
                uint32_t ba = (uint32_t)((np * 16 + bRow) * VROWB + t * 32 + bKof);
                uint32_t vbh[4];
                ldm_x4(vbh, kbase + OFF_VTH + ba);
                mma16816(oacc[np * 2],     pah[t], vbh[0], vbh[1]);
                mma16816(oacc[np * 2 + 1], pah[t], vbh[2], vbh[3]);
            }
        }
        __syncthreads();
    }

    float inv0 = 1.f / l0, inv1 = 1.f / l1;
    size_t row0 = (size_t)(b * SEQ + qrow0 + 16 * wid + g) * HIDDEN + hq * HD;
    size_t row1 = row0 + (size_t)8 * HIDDEN;
#pragma unroll
    for (int nd = 0; nd < 16; nd++) {
        int col = nd * 8 + 2 * tig;
        *(uint32_t*)(aoh + row0 + col) = pack_h2(
            __float2half_rn(oacc[nd][0] * inv0), __float2half_rn(oacc[nd][1] * inv0));
        *(uint32_t*)(aoh + row1 + col) = pack_h2(
            __float2half_rn(oacc[nd][2] * inv1), __float2half_rn(oacc[nd][3] * inv1));
    }
}

// ============================================================================
extern "C" void kernel_launch(void* const* d_in, const int* in_sizes, int n_in,
                              void* d_out, int out_size)
{
    const float* x  = (const float*)d_in[0];
    const float* Wq = (const float*)d_in[1];
    const float* Wk = (const float*)d_in[2];
    const float* Wv = (const float*)d_in[3];
    const float* Wo = (const float*)d_in[4];
    float* out = (float*)d_out;

    __half *xh, *wqh, *wkh, *wvh, *woh;
    __half *qh, *kh, *vh, *vth, *aoh;
    cudaGetSymbolAddress((void**)&xh,  g_xh);
    cudaGetSymbolAddress((void**)&wqh, g_wqh);
    cudaGetSymbolAddress((void**)&wkh, g_wkh);
    cudaGetSymbolAddress((void**)&wvh, g_wvh);
    cudaGetSymbolAddress((void**)&woh, g_woh);
    cudaGetSymbolAddress((void**)&qh,  g_qh);
    cudaGetSymbolAddress((void**)&kh,  g_kh);
    cudaGetSymbolAddress((void**)&vh,  g_vh);
    cudaGetSymbolAddress((void**)&vth, g_vth);
    cudaGetSymbolAddress((void**)&aoh, g_aoh);

    cudaFuncSetAttribute(qkv_hmma,   cudaFuncAttributeMaxDynamicSharedMemorySize, GEMM_SMEM);
    cudaFuncSetAttribute(gemm_wo,    cudaFuncAttributeMaxDynamicSharedMemorySize, WO_SMEM);
    cudaFuncSetAttribute(flash_hmma, cudaFuncAttributeMaxDynamicSharedMemorySize, FLASH_SMEM);

    split_all<<<(CVT_TOT + 255) / 256, 256>>>(
        (const float4*)x, (const float4*)Wq, (const float4*)Wk,
        (const float4*)Wv, (const float4*)Wo,
        (__half2*)xh, (__half2*)wqh, (__half2*)wkh, (__half2*)wvh, (__half2*)woh);

    qkv_hmma<<<dim3(6144 / BN, TOKENS / BM), 256, GEMM_SMEM>>>(
        xh, wqh, wkh, wvh, qh, kh, vh);

    transpose_v<<<dim3(SEQ / 32, KVDIM / 32, BATCH), 256>>>(vh, vth);

    flash_hmma<<<dim3(SEQ / 64, NH, BATCH), 128, FLASH_SMEM>>>(
        qh, kh, vth, aoh);

    gemm_wo<<<dim3(HIDDEN / WON, TOKENS / WOM), 256, WO_SMEM>>>(
        aoh, woh, out, HIDDEN, HIDDEN);
}

// round 16
// speedup vs baseline: 1.0961x; 1.0961x over previous
#include <cuda_runtime.h>
#include <cuda_fp16.h>
#include <cstdint>
#include <math.h>

#define HIDDEN   4096
#define NKV      8
#define NH       32
#define HD       128
#define BATCH    2
#define SEQ      2048
#define TOKENS   (BATCH*SEQ)   // 4096
#define KVDIM    (NKV*HD)      // 1024

// ---------------- scratch (device globals; no runtime allocation) ----------
__device__ __half g_xh [TOKENS*HIDDEN];
__device__ __half g_wqh[HIDDEN*HIDDEN];
__device__ __half g_wkh[KVDIM*HIDDEN];
__device__ __half g_wvh[KVDIM*HIDDEN];
__device__ __half g_woh[HIDDEN*HIDDEN];
__device__ __half g_qh [TOKENS*HIDDEN];
__device__ __half g_kh [TOKENS*KVDIM];
__device__ __half g_vh [TOKENS*KVDIM];
__device__ __half g_vth[TOKENS*KVDIM];                    // [B][KVDIM][SEQ]
__device__ __half g_aoh[TOKENS*HIDDEN];

// ======================= helpers ============================================
__device__ __forceinline__ uint32_t smem_u32(const void* p) {
    uint32_t a;
    asm("{ .reg .u64 t; cvta.to.shared.u64 t, %1; cvt.u32.u64 %0, t; }"
        : "=r"(a) : "l"(p));
    return a;
}
__device__ __forceinline__ void cp16(uint32_t dst, const void* src) {
    asm volatile("cp.async.cg.shared.global [%0], [%1], 16;" :: "r"(dst), "l"(src));
}
__device__ __forceinline__ void cp_commit() { asm volatile("cp.async.commit_group;" ::: "memory"); }
template<int N> __device__ __forceinline__ void cp_wait() {
    asm volatile("cp.async.wait_group %0;" :: "n"(N) : "memory");
}
__device__ __forceinline__ void ldm_x4(uint32_t* r, uint32_t addr) {
    asm volatile("ldmatrix.sync.aligned.m8n8.x4.shared.b16 {%0,%1,%2,%3}, [%4];"
        : "=r"(r[0]), "=r"(r[1]), "=r"(r[2]), "=r"(r[3]) : "r"(addr));
}
__device__ __forceinline__ void mma16816(float* d, const uint32_t* a,
                                         uint32_t b0, uint32_t b1) {
    asm volatile(
        "mma.sync.aligned.m16n8k16.row.col.f32.f16.f16.f32 "
        "{%0,%1,%2,%3}, {%4,%5,%6,%7}, {%8,%9}, {%0,%1,%2,%3};"
        : "+f"(d[0]), "+f"(d[1]), "+f"(d[2]), "+f"(d[3])
        : "r"(a[0]), "r"(a[1]), "r"(a[2]), "r"(a[3]), "r"(b0), "r"(b1));
}
__device__ __forceinline__ uint32_t pack_h2(__half a, __half b) {
    __half2 h = __halves2half2(a, b);
    return *(uint32_t*)&h;
}

// ======================= fp32 -> fp16 conversion (all tensors, one launch) ==
#define XN4 (TOKENS*HIDDEN/4)
#define WN4 (HIDDEN*HIDDEN/4)
#define KN4 (KVDIM*HIDDEN/4)
#define CVT_TOT (XN4 + 2*WN4 + 2*KN4)
__global__ __launch_bounds__(256) void split_all(
    const float4* __restrict__ x,
    const float4* __restrict__ wq, const float4* __restrict__ wk,
    const float4* __restrict__ wv, const float4* __restrict__ wo,
    __half2* __restrict__ xo,
    __half2* __restrict__ qo, __half2* __restrict__ ko,
    __half2* __restrict__ vo, __half2* __restrict__ oo)
{
    int i = blockIdx.x * blockDim.x + threadIdx.x;
    const float4* src;
    __half2* dst;
    int idx;
    if (i < XN4)                          { src = x;  dst = xo; idx = i; }
    else if (i < XN4 + WN4)               { src = wq; dst = qo; idx = i - XN4; }
    else if (i < XN4 + WN4 + KN4)         { src = wk; dst = ko; idx = i - XN4 - WN4; }
    else if (i < XN4 + WN4 + 2 * KN4)     { src = wv; dst = vo; idx = i - XN4 - WN4 - KN4; }
    else if (i < CVT_TOT)                 { src = wo; dst = oo; idx = i - XN4 - WN4 - 2 * KN4; }
    else return;
    float4 v = src[idx];
    dst[2 * idx]     = __halves2half2(__float2half_rn(v.x), __float2half_rn(v.y));
    dst[2 * idx + 1] = __halves2half2(__float2half_rn(v.z), __float2half_rn(v.w));
}

// ======================= GEMM (single-term, 128x128 tile, 2 CTAs/SM) ========
#define BM 128
#define BN 128
#define BK 64
#define ROWB 144
#define A_ST (BM*ROWB)                 // 18432
#define B_ST (BN*ROWB)                 // 18432
#define STAGE_B (A_ST + B_ST)          // 36864
#define NSTAGE 3
#define GEMM_SMEM (NSTAGE*STAGE_B)     // 110592

// swizzled block mapping (supertiles of 8 m-blocks)
__device__ __forceinline__ void cta_map(int gx, int gy, int& mb, int& nb) {
    int lin = blockIdx.y * gx + blockIdx.x;
    const int SW = 8;
    int per  = SW * gx;
    int band = lin / per;
    int rem  = lin - band * per;
    int h    = gy - band * SW; if (h > SW) h = SW;
    mb = band * SW + rem % h;
    nb = rem / h;
}

// core: C[128,128] = A[128,K] @ B[128,K]^T, single fp16 term
// out: split==2 -> fp16 hi; split==0 -> fp32
__device__ __forceinline__ void gemm1_core(
    uint32_t sbase, const __half* A0, const __half* B0,
    int m0, int ncol0, int K,
    float* C, __half* Ch, int Nout, int split)
{
    const int tid  = threadIdx.x;
    const int wid  = tid >> 5;
    const int lane = tid & 31;
    const int warpM = (wid & 1) * 64;
    const int warpN = (wid >> 1) * 32;

    auto bA = [&](int s) { return sbase + s * STAGE_B; };
    auto bB = [&](int s) { return sbase + s * STAGE_B + A_ST; };

    auto load_stage = [&](int s, int k0) {
#pragma unroll
        for (int t = 0; t < 4; t++) {                // A: 1024 chunks
            int idx = tid + t * 256;
            int r = idx >> 3, c = idx & 7;
            uint32_t d = (uint32_t)(r * ROWB + c * 16);
            cp16(bA(s) + d, A0 + (size_t)r * K + k0 + c * 8);
        }
#pragma unroll
        for (int t = 0; t < 4; t++) {                // B: 1024 chunks
            int idx = tid + t * 256;
            int r = idx >> 3, c = idx & 7;
            uint32_t d = (uint32_t)(r * ROWB + c * 16);
            cp16(bB(s) + d, B0 + (size_t)r * K + k0 + c * 8);
        }
    };

    float acc[4][4][4];
#pragma unroll
    for (int i = 0; i < 4; i++)
#pragma unroll
        for (int j = 0; j < 4; j++)
#pragma unroll
            for (int t = 0; t < 4; t++) acc[i][j][t] = 0.f;

    const int aRow = lane & 15;
    const int aKof = (lane >> 4) * 16;
    const int bRow = (lane & 7) + ((lane & 16) ? 8 : 0);
    const int bKof = (lane & 8) ? 16 : 0;

    const int nst = K / BK;
    load_stage(0, 0);
    cp_commit();
    load_stage(1, BK);
    cp_commit();

    for (int s = 0; s < nst; s++) {
        const int buf = s % NSTAGE;
        if (s + 1 < nst) cp_wait<1>(); else cp_wait<0>();
        __syncthreads();

        const uint32_t sA = bA(buf), sB = bB(buf);

#pragma unroll
        for (int ks = 0; ks < 4; ks++) {
            const int kb = ks * 32;
            uint32_t ah[4][4], bh[2][4];
#pragma unroll
            for (int mi = 0; mi < 4; mi++) {
                uint32_t ad = (uint32_t)((warpM + mi * 16 + aRow) * ROWB + kb + aKof);
                ldm_x4(ah[mi], sA + ad);
            }
#pragma unroll
            for (int np = 0; np < 2; np++) {
                uint32_t bd = (uint32_t)((warpN + np * 16 + bRow) * ROWB + kb + bKof);
                ldm_x4(bh[np], sB + bd);
            }
#pragma unroll
            for (int np = 0; np < 2; np++)
#pragma unroll
                for (int q = 0; q < 2; q++) {
                    const int ni = np * 2 + q;
                    const uint32_t b0 = bh[np][q * 2], b1 = bh[np][q * 2 + 1];
#pragma unroll
                    for (int mi = 0; mi < 4; mi++)
                        mma16816(acc[mi][ni], ah[mi], b0, b1);
                }
        }

        if (s + 2 < nst) {
            load_stage((s + 2) % NSTAGE, (s + 2) * BK);
            cp_commit();
        }
    }

    const int er = lane >> 2;
    const int ec = (lane & 3) * 2;
    if (split == 2) {
#pragma unroll
        for (int mi = 0; mi < 4; mi++)
#pragma unroll
            for (int ni = 0; ni < 4; ni++) {
                size_t off0 = (size_t)(m0 + warpM + mi * 16 + er) * Nout
                            + (ncol0 + warpN + ni * 8 + ec);
                size_t off1 = off0 + (size_t)8 * Nout;
                *(uint32_t*)(Ch + off0) = pack_h2(
                    __float2half_rn(acc[mi][ni][0]), __float2half_rn(acc[mi][ni][1]));
                *(uint32_t*)(Ch + off1) = pack_h2(
                    __float2half_rn(acc[mi][ni][2]), __float2half_rn(acc[mi][ni][3]));
            }
    } else {
#pragma unroll
        for (int mi = 0; mi < 4; mi++)
#pragma unroll
            for (int ni = 0; ni < 4; ni++) {
                float* p = C + (size_t)(m0 + warpM + mi * 16 + er) * Nout
                             + (ncol0 + warpN + ni * 8 + ec);
                p[0] = acc[mi][ni][0];
                p[1] = acc[mi][ni][1];
                float* q = p + (size_t)8 * Nout;
                q[0] = acc[mi][ni][2];
                q[1] = acc[mi][ni][3];
            }
    }
}

// fused QKV projection: virtual N = 6144 -> 48 n-blocks (Q 32 | K 8 | V 8)
__global__ __launch_bounds__(256, 2) void qkv_hmma(
    const __half* __restrict__ xh,
    const __half* __restrict__ wqh,
    const __half* __restrict__ wkh,
    const __half* __restrict__ wvh,
    __half* __restrict__ qh,
    __half* __restrict__ kh,
    __half* __restrict__ vh)
{
    extern __shared__ char smraw[];
    const uint32_t sbase = smem_u32(smraw);
    int mb, nb;
    cta_map(gridDim.x, gridDim.y, mb, nb);
    const int m0 = mb * BM;

    const __half* Bh_;
    __half* Ch;
    int Nout, ncol;
    if (nb < 32)      { Bh_ = wqh; Ch = qh; Nout = HIDDEN; ncol = nb * BN; }
    else if (nb < 40) { Bh_ = wkh; Ch = kh; Nout = KVDIM;  ncol = (nb - 32) * BN; }
    else              { Bh_ = wvh; Ch = vh; Nout = KVDIM;  ncol = (nb - 40) * BN; }

    gemm1_core(sbase, xh + (size_t)m0 * HIDDEN, Bh_ + (size_t)ncol * HIDDEN,
               m0, ncol, HIDDEN, nullptr, Ch, Nout, 2);
}

__global__ __launch_bounds__(256, 2) void gemm_wo(
    const __half* __restrict__ Ah, const __half* __restrict__ Bh,
    float* __restrict__ C, int N, int K)
{
    extern __shared__ char smraw[];
    const uint32_t sbase = smem_u32(smraw);
    int mb, nb;
    cta_map(gridDim.x, gridDim.y, mb, nb);
    const int m0 = mb * BM, n0 = nb * BN;
    gemm1_core(sbase, Ah + (size_t)m0 * K, Bh + (size_t)n0 * K,
               m0, n0, K, C, nullptr, N, 0);
}

// ======================= V transpose (hi only) ==============================
__global__ __launch_bounds__(256) void transpose_v(
    const __half* __restrict__ vh, __half* __restrict__ vth)
{
    __shared__ __half th[32][33];
    const int b  = blockIdx.z;
    const int k0 = blockIdx.y * 32;
    const int s0 = blockIdx.x * 32;
    const int tx = threadIdx.x & 31;
    const int ty = threadIdx.x >> 5;
#pragma unroll
    for (int i = 0; i < 4; i++) {
        int row = ty + i * 8;
        th[row][tx] = vh[(size_t)(b * SEQ + s0 + row) * KVDIM + k0 + tx];
    }
    __syncthreads();
#pragma unroll
    for (int i = 0; i < 4; i++) {
        int row = ty + i * 8;
        vth[((size_t)b * KVDIM + k0 + row) * SEQ + s0 + tx] = th[tx][row];
    }
}

// ======================= HMMA flash attention (R14 config) ===================
// 128 q-rows/CTA, 256 threads, 128-col kv blocks.
// QK: Qh*Kh.  PV: Ph*Vh.  Softmax in log2 domain.
#define QROWB 272
#define KROWB 272
#define VROWB 272
#define SKV_BASE  34816
#define K_TILE_B  (128*KROWB)          // 34816
#define V_TILE_B  (128*VROWB)          // 34816
#define SKV_STRIDE (K_TILE_B + V_TILE_B)  // 69632
#define OFF_KH 0
#define OFF_VTH K_TILE_B
#define FLASH_SMEM (SKV_BASE + 2*SKV_STRIDE)   // 174080

__global__ __launch_bounds__(256, 1) void flash_hmma(
    const __half* __restrict__ qh,
    const __half* __restrict__ kh,
    const __half* __restrict__ vth,
    __half* __restrict__ aoh)
{
    extern __shared__ char smraw[];
    const uint32_t sb = smem_u32(smraw);
    const int tid = threadIdx.x, wid = tid >> 5, lane = tid & 31;
    const int qb = (int)(gridDim.x - 1 - blockIdx.x);
    const int hq = blockIdx.y, b = blockIdx.z;
    const int kvh = hq >> 2;
    const int qrow0 = qb * 128;
    const int g = lane >> 2, tig = lane & 3;
    const float cs = 0.08838834764831845f * 1.4426950408889634f;

    const __half* qhg = qh + (size_t)(b * SEQ + qrow0) * HIDDEN + hq * HD;
#pragma unroll
    for (int t = 0; t < 8; t++) {
        int idx = tid + t * 256;
        int r = idx >> 4, c = idx & 15;
        cp16(sb + (uint32_t)(r * QROWB + c * 16), qhg + (size_t)r * HIDDEN + c * 8);
    }
    cp_commit();

    const __half* khg = kh + (size_t)(b * SEQ) * KVDIM + kvh * HD;
    const __half* vthg = vth + ((size_t)b * KVDIM + kvh * HD) * SEQ;

    auto load_kv = [&](int stage, int j) {
        uint32_t base = sb + SKV_BASE + stage * SKV_STRIDE;
        int c0 = j * 128;
#pragma unroll
        for (int t = 0; t < 8; t++) {
            int idx = tid + t * 256;
            int r = idx >> 4, c = idx & 15;
            uint32_t d = (uint32_t)(r * KROWB + c * 16);
            cp16(base + OFF_KH + d, khg + (size_t)(c0 + r) * KVDIM + c * 8);
        }
#pragma unroll
        for (int t = 0; t < 8; t++) {
            int idx = tid + t * 256;
            int r = idx >> 4, c = idx & 15;
            uint32_t d = (uint32_t)(r * VROWB + c * 16);
            cp16(base + OFF_VTH + d, vthg + (size_t)r * SEQ + c0 + c * 8);
        }
    };

    const int nb = qb + 1;
    load_kv(0, 0);
    cp_commit();

    float oacc[16][4];
#pragma unroll
    for (int i = 0; i < 16; i++)
#pragma unroll
        for (int t = 0; t < 4; t++) oacc[i][t] = 0.f;
    float m0 = -1e30f, m1 = -1e30f, l0 = 0.f, l1 = 0.f;

    const int aRow = lane & 15;
    const int aKof = (lane >> 4) * 16;
    const int bRow = (lane & 7) + ((lane & 16) ? 8 : 0);
    const int bKof = (lane & 8) ? 16 : 0;

    const int rg0 = qrow0 + 16 * wid + g;
    const int rg1 = rg0 + 8;

    for (int j = 0; j < nb; j++) {
        const int buf = j & 1;
        if (j + 1 < nb) {
            load_kv(1 - buf, j + 1);
            cp_commit();
            cp_wait<1>();
        } else {
            cp_wait<0>();
        }
        __syncthreads();

        const uint32_t kbase = sb + SKV_BASE + buf * SKV_STRIDE;

        float sacc[16][4];
#pragma unroll
        for (int i = 0; i < 16; i++)
#pragma unroll
            for (int t = 0; t < 4; t++) sacc[i][t] = 0.f;

#pragma unroll
        for (int kd = 0; kd < 8; kd++) {
            uint32_t aa = (uint32_t)((16 * wid + aRow) * QROWB + kd * 32 + aKof);
            uint32_t ah[4];
            ldm_x4(ah, sb + aa);
#pragma unroll
            for (int np = 0; np < 8; np++) {
                uint32_t ba = (uint32_t)((np * 16 + bRow) * KROWB + kd * 32 + bKof);
                uint32_t bh[4];
                ldm_x4(bh, kbase + OFF_KH + ba);
                mma16816(sacc[np * 2],     ah, bh[0], bh[1]);
                mma16816(sacc[np * 2 + 1], ah, bh[2], bh[3]);
            }
        }

        const int c0 = j * 128;
        if (j == nb - 1 && j == qb) {
#pragma unroll
            for (int ni = 0; ni < 16; ni++) {
                int cg = c0 + ni * 8 + 2 * tig;
                if (cg     > rg0) sacc[ni][0] = -1e30f;
                if (cg + 1 > rg0) sacc[ni][1] = -1e30f;
                if (cg     > rg1) sacc[ni][2] = -1e30f;
                if (cg + 1 > rg1) sacc[ni][3] = -1e30f;
            }
        }

        float vm0 = -1e30f, vm1 = -1e30f;
#pragma unroll
        for (int ni = 0; ni < 16; ni++) {
            vm0 = fmaxf(vm0, fmaxf(sacc[ni][0], sacc[ni][1]));
            vm1 = fmaxf(vm1, fmaxf(sacc[ni][2], sacc[ni][3]));
        }
        vm0 = fmaxf(vm0, __shfl_xor_sync(0xffffffffu, vm0, 1));
        vm0 = fmaxf(vm0, __shfl_xor_sync(0xffffffffu, vm0, 2));
        vm1 = fmaxf(vm1, __shfl_xor_sync(0xffffffffu, vm1, 1));
        vm1 = fmaxf(vm1, __shfl_xor_sync(0xffffffffu, vm1, 2));
        float mn0 = fmaxf(m0, vm0 * cs), mn1 = fmaxf(m1, vm1 * cs);
        float al0 = exp2f(m0 - mn0), al1 = exp2f(m1 - mn1);
        float sum0 = 0.f, sum1 = 0.f;
#pragma unroll
        for (int ni = 0; ni < 16; ni++) {
            sacc[ni][0] = exp2f(fmaf(sacc[ni][0], cs, -mn0));
            sacc[ni][1] = exp2f(fmaf(sacc[ni][1], cs, -mn0));
            sacc[ni][2] = exp2f(fmaf(sacc[ni][2], cs, -mn1));
            sacc[ni][3] = exp2f(fmaf(sacc[ni][3], cs, -mn1));
            sum0 += sacc[ni][0] + sacc[ni][1];
            sum1 += sacc[ni][2] + sacc[ni][3];
        }
        sum0 += __shfl_xor_sync(0xffffffffu, sum0, 1);
        sum0 += __shfl_xor_sync(0xffffffffu, sum0, 2);
        sum1 += __shfl_xor_sync(0xffffffffu, sum1, 1);
        sum1 += __shfl_xor_sync(0xffffffffu, sum1, 2);
        l0 = l0 * al0 + sum0;  l1 = l1 * al1 + sum1;
        m0 = mn0;  m1 = mn1;

#pragma unroll
        for (int nd = 0; nd < 16; nd++) {
            oacc[nd][0] *= al0;  oacc[nd][1] *= al0;
            oacc[nd][2] *= al1;  oacc[nd][3] *= al1;
        }

        uint32_t pah[8][4];
#pragma unroll
        for (int t = 0; t < 8; t++) {
            pah[t][0] = pack_h2(__float2half_rn(sacc[2 * t][0]),
                                __float2half_rn(sacc[2 * t][1]));
            pah[t][1] = pack_h2(__float2half_rn(sacc[2 * t][2]),
                                __float2half_rn(sacc[2 * t][3]));
            pah[t][2] = pack_h2(__float2half_rn(sacc[2 * t + 1][0]),
                                __float2half_rn(sacc[2 * t + 1][1]));
            pah[t][3] = pack_h2(__float2half_rn(sacc[2 * t + 1][2]),
                                __float2half_rn(sacc[2 * t + 1][3]));
        }

#pragma unroll
        for (int t = 0; t < 8; t++) {
#pragma unroll
            for (int np = 0; np < 8; np++) {
                uint32_t ba = (uint32_t)((np * 16 + bRow) * VROWB + t * 32 + bKof);
                uint32_t vbh[4];
                ldm_x4(vbh, kbase + OFF_VTH + ba);
                mma16816(oacc[np * 2],     pah[t], vbh[0], vbh[1]);
                mma16816(oacc[np * 2 + 1], pah[t], vbh[2], vbh[3]);
            }
        }
        __syncthreads();
    }

    float inv0 = 1.f / l0, inv1 = 1.f / l1;
    size_t row0 = (size_t)(b * SEQ + qrow0 + 16 * wid + g) * HIDDEN + hq * HD;
    size_t row1 = row0 + (size_t)8 * HIDDEN;
#pragma unroll
    for (int nd = 0; nd < 16; nd++) {
        int col = nd * 8 + 2 * tig;
        *(uint32_t*)(aoh + row0 + col) = pack_h2(
            __float2half_rn(oacc[nd][0] * inv0), __float2half_rn(oacc[nd][1] * inv0));
        *(uint32_t*)(aoh + row1 + col) = pack_h2(
            __float2half_rn(oacc[nd][2] * inv1), __float2half_rn(oacc[nd][3] * inv1));
    }
}

// ============================================================================
extern "C" void kernel_launch(void* const* d_in, const int* in_sizes, int n_in,
                              void* d_out, int out_size)
{
    const float* x  = (const float*)d_in[0];
    const float* Wq = (const float*)d_in[1];
    const float* Wk = (const float*)d_in[2];
    const float* Wv = (const float*)d_in[3];
    const float* Wo = (const float*)d_in[4];
    float* out = (float*)d_out;

    __half *xh, *wqh, *wkh, *wvh, *woh;
    __half *qh, *kh, *vh, *vth, *aoh;
    cudaGetSymbolAddress((void**)&xh,  g_xh);
    cudaGetSymbolAddress((void**)&wqh, g_wqh);
    cudaGetSymbolAddress((void**)&wkh, g_wkh);
    cudaGetSymbolAddress((void**)&wvh, g_wvh);
    cudaGetSymbolAddress((void**)&woh, g_woh);
    cudaGetSymbolAddress((void**)&qh,  g_qh);
    cudaGetSymbolAddress((void**)&kh,  g_kh);
    cudaGetSymbolAddress((void**)&vh,  g_vh);
    cudaGetSymbolAddress((void**)&vth, g_vth);
    cudaGetSymbolAddress((void**)&aoh, g_aoh);

    cudaFuncSetAttribute(qkv_hmma,   cudaFuncAttributeMaxDynamicSharedMemorySize, GEMM_SMEM);
    cudaFuncSetAttribute(gemm_wo,    cudaFuncAttributeMaxDynamicSharedMemorySize, GEMM_SMEM);
    cudaFuncSetAttribute(flash_hmma, cudaFuncAttributeMaxDynamicSharedMemorySize, FLASH_SMEM);

    split_all<<<(CVT_TOT + 255) / 256, 256>>>(
        (const float4*)x, (const float4*)Wq, (const float4*)Wk,
        (const float4*)Wv, (const float4*)Wo,
        (__half2*)xh, (__half2*)wqh, (__half2*)wkh, (__half2*)wvh, (__half2*)woh);

    qkv_hmma<<<dim3(6144 / BN, TOKENS / BM), 256, GEMM_SMEM>>>(
        xh, wqh, wkh, wvh, qh, kh, vh);

    transpose_v<<<dim3(SEQ / 32, KVDIM / 32, BATCH), 256>>>(vh, vth);

    flash_hmma<<<dim3(SEQ / 128, NH, BATCH), 256, FLASH_SMEM>>>(
        qh, kh, vth, aoh);

    gemm_wo<<<dim3(HIDDEN / BN, TOKENS / BM), 256, GEMM_SMEM>>>(
        aoh, woh, out, HIDDEN, HIDDEN);
}

// round 17
// speedup vs baseline: 1.1142x; 1.0166x over previous
#include <cuda_runtime.h>
#include <cuda_fp16.h>
#include <cstdint>
#include <math.h>

#define HIDDEN   4096
#define NKV      8
#define NH       32
#define HD       128
#define BATCH    2
#define SEQ      2048
#define TOKENS   (BATCH*SEQ)   // 4096
#define KVDIM    (NKV*HD)      // 1024

// ---------------- scratch (device globals; no runtime allocation) ----------
__device__ __half g_xh [TOKENS*HIDDEN];
__device__ __half g_wqh[HIDDEN*HIDDEN];
__device__ __half g_wkh[KVDIM*HIDDEN];
__device__ __half g_wvh[KVDIM*HIDDEN];
__device__ __half g_woh[HIDDEN*HIDDEN];
__device__ __half g_qh [TOKENS*HIDDEN];
__device__ __half g_kh [TOKENS*KVDIM];
__device__ __half g_vh [TOKENS*KVDIM];
__device__ __half g_aoh[TOKENS*HIDDEN];

// ======================= helpers ============================================
__device__ __forceinline__ uint32_t smem_u32(const void* p) {
    uint32_t a;
    asm("{ .reg .u64 t; cvta.to.shared.u64 t, %1; cvt.u32.u64 %0, t; }"
        : "=r"(a) : "l"(p));
    return a;
}
__device__ __forceinline__ void cp16(uint32_t dst, const void* src) {
    asm volatile("cp.async.cg.shared.global [%0], [%1], 16;" :: "r"(dst), "l"(src));
}
__device__ __forceinline__ void cp_commit() { asm volatile("cp.async.commit_group;" ::: "memory"); }
template<int N> __device__ __forceinline__ void cp_wait() {
    asm volatile("cp.async.wait_group %0;" :: "n"(N) : "memory");
}
__device__ __forceinline__ void ldm_x4(uint32_t* r, uint32_t addr) {
    asm volatile("ldmatrix.sync.aligned.m8n8.x4.shared.b16 {%0,%1,%2,%3}, [%4];"
        : "=r"(r[0]), "=r"(r[1]), "=r"(r[2]), "=r"(r[3]) : "r"(addr));
}
__device__ __forceinline__ void ldm_x4_t(uint32_t* r, uint32_t addr) {
    asm volatile("ldmatrix.sync.aligned.m8n8.x4.trans.shared.b16 {%0,%1,%2,%3}, [%4];"
        : "=r"(r[0]), "=r"(r[1]), "=r"(r[2]), "=r"(r[3]) : "r"(addr));
}
__device__ __forceinline__ void mma16816(float* d, const uint32_t* a,
                                         uint32_t b0, uint32_t b1) {
    asm volatile(
        "mma.sync.aligned.m16n8k16.row.col.f32.f16.f16.f32 "
        "{%0,%1,%2,%3}, {%4,%5,%6,%7}, {%8,%9}, {%0,%1,%2,%3};"
        : "+f"(d[0]), "+f"(d[1]), "+f"(d[2]), "+f"(d[3])
        : "r"(a[0]), "r"(a[1]), "r"(a[2]), "r"(a[3]), "r"(b0), "r"(b1));
}
__device__ __forceinline__ uint32_t pack_h2(__half a, __half b) {
    __half2 h = __halves2half2(a, b);
    return *(uint32_t*)&h;
}

// ======================= fp32 -> fp16 conversion (wide, one launch) =========
// Each thread converts 8 floats: 2x float4 loads -> 1x uint4 (STG.128) store.
#define XN8 (TOKENS*HIDDEN/8)
#define WN8 (HIDDEN*HIDDEN/8)
#define KN8 (KVDIM*HIDDEN/8)
#define CVT_TOT (XN8 + 2*WN8 + 2*KN8)
__global__ __launch_bounds__(256) void split_all(
    const float4* __restrict__ x,
    const float4* __restrict__ wq, const float4* __restrict__ wk,
    const float4* __restrict__ wv, const float4* __restrict__ wo,
    __half2* __restrict__ xo,
    __half2* __restrict__ qo, __half2* __restrict__ ko,
    __half2* __restrict__ vo, __half2* __restrict__ oo)
{
    int i = blockIdx.x * blockDim.x + threadIdx.x;
    const float4* src;
    __half2* dst;
    int idx;
    if (i < XN8)                          { src = x;  dst = xo; idx = i; }
    else if (i < XN8 + WN8)               { src = wq; dst = qo; idx = i - XN8; }
    else if (i < XN8 + WN8 + KN8)         { src = wk; dst = ko; idx = i - XN8 - WN8; }
    else if (i < XN8 + WN8 + 2 * KN8)     { src = wv; dst = vo; idx = i - XN8 - WN8 - KN8; }
    else if (i < CVT_TOT)                 { src = wo; dst = oo; idx = i - XN8 - WN8 - 2 * KN8; }
    else return;
    float4 a = src[2 * idx];
    float4 b = src[2 * idx + 1];
    uint4 o;
    o.x = pack_h2(__float2half_rn(a.x), __float2half_rn(a.y));
    o.y = pack_h2(__float2half_rn(a.z), __float2half_rn(a.w));
    o.z = pack_h2(__float2half_rn(b.x), __float2half_rn(b.y));
    o.w = pack_h2(__float2half_rn(b.z), __float2half_rn(b.w));
    *(uint4*)(dst + 4 * (size_t)idx) = o;
}

// ======================= GEMM (single-term, 128x128 tile, 2 CTAs/SM) ========
#define BM 128
#define BN 128
#define BK 64
#define ROWB 144
#define A_ST (BM*ROWB)                 // 18432
#define B_ST (BN*ROWB)                 // 18432
#define STAGE_B (A_ST + B_ST)          // 36864
#define NSTAGE 3
#define GEMM_SMEM (NSTAGE*STAGE_B)     // 110592

// swizzled block mapping (supertiles of 8 m-blocks)
__device__ __forceinline__ void cta_map(int gx, int gy, int& mb, int& nb) {
    int lin = blockIdx.y * gx + blockIdx.x;
    const int SW = 8;
    int per  = SW * gx;
    int band = lin / per;
    int rem  = lin - band * per;
    int h    = gy - band * SW; if (h > SW) h = SW;
    mb = band * SW + rem % h;
    nb = rem / h;
}

__device__ __forceinline__ void gemm1_core(
    uint32_t sbase, const __half* A0, const __half* B0,
    int m0, int ncol0, int K,
    float* C, __half* Ch, int Nout, int split)
{
    const int tid  = threadIdx.x;
    const int wid  = tid >> 5;
    const int lane = tid & 31;
    const int warpM = (wid & 1) * 64;
    const int warpN = (wid >> 1) * 32;

    auto bA = [&](int s) { return sbase + s * STAGE_B; };
    auto bB = [&](int s) { return sbase + s * STAGE_B + A_ST; };

    auto load_stage = [&](int s, int k0) {
#pragma unroll
        for (int t = 0; t < 4; t++) {
            int idx = tid + t * 256;
            int r = idx >> 3, c = idx & 7;
            uint32_t d = (uint32_t)(r * ROWB + c * 16);
            cp16(bA(s) + d, A0 + (size_t)r * K + k0 + c * 8);
        }
#pragma unroll
        for (int t = 0; t < 4; t++) {
            int idx = tid + t * 256;
            int r = idx >> 3, c = idx & 7;
            uint32_t d = (uint32_t)(r * ROWB + c * 16);
            cp16(bB(s) + d, B0 + (size_t)r * K + k0 + c * 8);
        }
    };

    float acc[4][4][4];
#pragma unroll
    for (int i = 0; i < 4; i++)
#pragma unroll
        for (int j = 0; j < 4; j++)
#pragma unroll
            for (int t = 0; t < 4; t++) acc[i][j][t] = 0.f;

    const int aRow = lane & 15;
    const int aKof = (lane >> 4) * 16;
    const int bRow = (lane & 7) + ((lane & 16) ? 8 : 0);
    const int bKof = (lane & 8) ? 16 : 0;

    const int nst = K / BK;
    load_stage(0, 0);
    cp_commit();
    load_stage(1, BK);
    cp_commit();

    for (int s = 0; s < nst; s++) {
        const int buf = s % NSTAGE;
        if (s + 1 < nst) cp_wait<1>(); else cp_wait<0>();
        __syncthreads();

        const uint32_t sA = bA(buf), sB = bB(buf);

#pragma unroll
        for (int ks = 0; ks < 4; ks++) {
            const int kb = ks * 32;
            uint32_t ah[4][4], bh[2][4];
#pragma unroll
            for (int mi = 0; mi < 4; mi++) {
                uint32_t ad = (uint32_t)((warpM + mi * 16 + aRow) * ROWB + kb + aKof);
                ldm_x4(ah[mi], sA + ad);
            }
#pragma unroll
            for (int np = 0; np < 2; np++) {
                uint32_t bd = (uint32_t)((warpN + np * 16 + bRow) * ROWB + kb + bKof);
                ldm_x4(bh[np], sB + bd);
            }
#pragma unroll
            for (int np = 0; np < 2; np++)
#pragma unroll
                for (int q = 0; q < 2; q++) {
                    const int ni = np * 2 + q;
                    const uint32_t b0 = bh[np][q * 2], b1 = bh[np][q * 2 + 1];
#pragma unroll
                    for (int mi = 0; mi < 4; mi++)
                        mma16816(acc[mi][ni], ah[mi], b0, b1);
                }
        }

        if (s + 2 < nst) {
            load_stage((s + 2) % NSTAGE, (s + 2) * BK);
            cp_commit();
        }
    }

    const int er = lane >> 2;
    const int ec = (lane & 3) * 2;
    if (split == 2) {
#pragma unroll
        for (int mi = 0; mi < 4; mi++)
#pragma unroll
            for (int ni = 0; ni < 4; ni++) {
                size_t off0 = (size_t)(m0 + warpM + mi * 16 + er) * Nout
                            + (ncol0 + warpN + ni * 8 + ec);
                size_t off1 = off0 + (size_t)8 * Nout;
                *(uint32_t*)(Ch + off0) = pack_h2(
                    __float2half_rn(acc[mi][ni][0]), __float2half_rn(acc[mi][ni][1]));
                *(uint32_t*)(Ch + off1) = pack_h2(
                    __float2half_rn(acc[mi][ni][2]), __float2half_rn(acc[mi][ni][3]));
            }
    } else {
#pragma unroll
        for (int mi = 0; mi < 4; mi++)
#pragma unroll
            for (int ni = 0; ni < 4; ni++) {
                float* p = C + (size_t)(m0 + warpM + mi * 16 + er) * Nout
                             + (ncol0 + warpN + ni * 8 + ec);
                p[0] = acc[mi][ni][0];
                p[1] = acc[mi][ni][1];
                float* q = p + (size_t)8 * Nout;
                q[0] = acc[mi][ni][2];
                q[1] = acc[mi][ni][3];
            }
    }
}

// fused QKV projection: virtual N = 6144 -> 48 n-blocks (Q 32 | K 8 | V 8)
__global__ __launch_bounds__(256, 2) void qkv_hmma(
    const __half* __restrict__ xh,
    const __half* __restrict__ wqh,
    const __half* __restrict__ wkh,
    const __half* __restrict__ wvh,
    __half* __restrict__ qh,
    __half* __restrict__ kh,
    __half* __restrict__ vh)
{
    extern __shared__ char smraw[];
    const uint32_t sbase = smem_u32(smraw);
    int mb, nb;
    cta_map(gridDim.x, gridDim.y, mb, nb);
    const int m0 = mb * BM;

    const __half* Bh_;
    __half* Ch;
    int Nout, ncol;
    if (nb < 32)      { Bh_ = wqh; Ch = qh; Nout = HIDDEN; ncol = nb * BN; }
    else if (nb < 40) { Bh_ = wkh; Ch = kh; Nout = KVDIM;  ncol = (nb - 32) * BN; }
    else              { Bh_ = wvh; Ch = vh; Nout = KVDIM;  ncol = (nb - 40) * BN; }

    gemm1_core(sbase, xh + (size_t)m0 * HIDDEN, Bh_ + (size_t)ncol * HIDDEN,
               m0, ncol, HIDDEN, nullptr, Ch, Nout, 2);
}

__global__ __launch_bounds__(256, 2) void gemm_wo(
    const __half* __restrict__ Ah, const __half* __restrict__ Bh,
    float* __restrict__ C, int N, int K)
{
    extern __shared__ char smraw[];
    const uint32_t sbase = smem_u32(smraw);
    int mb, nb;
    cta_map(gridDim.x, gridDim.y, mb, nb);
    const int m0 = mb * BM, n0 = nb * BN;
    gemm1_core(sbase, Ah + (size_t)m0 * K, Bh + (size_t)n0 * K,
               m0, n0, K, C, nullptr, N, 0);
}

// ======================= HMMA flash attention ================================
// 128 q-rows/CTA, 256 threads, 128-col kv blocks. V loaded row-major [kv, d],
// PV B-operand via ldmatrix.trans (no V transpose pass needed).
// QK: Qh*Kh.  PV: Ph*Vh.  Softmax in log2 domain.
#define QROWB 272
#define KROWB 272
#define VROWB 272
#define SKV_BASE  34816
#define K_TILE_B  (128*KROWB)          // 34816
#define V_TILE_B  (128*VROWB)          // 34816
#define SKV_STRIDE (K_TILE_B + V_TILE_B)  // 69632
#define OFF_KH 0
#define OFF_V  K_TILE_B
#define FLASH_SMEM (SKV_BASE + 2*SKV_STRIDE)   // 174080

__global__ __launch_bounds__(256, 1) void flash_hmma(
    const __half* __restrict__ qh,
    const __half* __restrict__ kh,
    const __half* __restrict__ vh,
    __half* __restrict__ aoh)
{
    extern __shared__ char smraw[];
    const uint32_t sb = smem_u32(smraw);
    const int tid = threadIdx.x, wid = tid >> 5, lane = tid & 31;
    const int qb = (int)(gridDim.x - 1 - blockIdx.x);
    const int hq = blockIdx.y, b = blockIdx.z;
    const int kvh = hq >> 2;
    const int qrow0 = qb * 128;
    const int g = lane >> 2, tig = lane & 3;
    const float cs = 0.08838834764831845f * 1.4426950408889634f;

    const __half* qhg = qh + (size_t)(b * SEQ + qrow0) * HIDDEN + hq * HD;
#pragma unroll
    for (int t = 0; t < 8; t++) {
        int idx = tid + t * 256;
        int r = idx >> 4, c = idx & 15;
        cp16(sb + (uint32_t)(r * QROWB + c * 16), qhg + (size_t)r * HIDDEN + c * 8);
    }
    cp_commit();

    const __half* khg = kh + (size_t)(b * SEQ) * KVDIM + kvh * HD;
    const __half* vhg = vh + (size_t)(b * SEQ) * KVDIM + kvh * HD;

    auto load_kv = [&](int stage, int j) {
        uint32_t base = sb + SKV_BASE + stage * SKV_STRIDE;
        int c0 = j * 128;
#pragma unroll
        for (int t = 0; t < 8; t++) {                 // K: 128 rows x 16 chunks
            int idx = tid + t * 256;
            int r = idx >> 4, c = idx & 15;
            uint32_t d = (uint32_t)(r * KROWB + c * 16);
            cp16(base + OFF_KH + d, khg + (size_t)(c0 + r) * KVDIM + c * 8);
        }
#pragma unroll
        for (int t = 0; t < 8; t++) {                 // V: 128 rows x 16 chunks
            int idx = tid + t * 256;
            int r = idx >> 4, c = idx & 15;
            uint32_t d = (uint32_t)(r * VROWB + c * 16);
            cp16(base + OFF_V + d, vhg + (size_t)(c0 + r) * KVDIM + c * 8);
        }
    };

    const int nb = qb + 1;
    load_kv(0, 0);
    cp_commit();

    float oacc[16][4];
#pragma unroll
    for (int i = 0; i < 16; i++)
#pragma unroll
        for (int t = 0; t < 4; t++) oacc[i][t] = 0.f;
    float m0 = -1e30f, m1 = -1e30f, l0 = 0.f, l1 = 0.f;

    const int aRow = lane & 15;
    const int aKof = (lane >> 4) * 16;
    const int bRow = (lane & 7) + ((lane & 16) ? 8 : 0);
    const int bKof = (lane & 8) ? 16 : 0;
    const int vRow = lane & 15;                       // trans-load: kv row in tile
    const int vKof = (lane & 16) ? 16 : 0;            // +8 d-cols for 2nd n8

    const int rg0 = qrow0 + 16 * wid + g;
    const int rg1 = rg0 + 8;

    for (int j = 0; j < nb; j++) {
        const int buf = j & 1;
        if (j + 1 < nb) {
            load_kv(1 - buf, j + 1);
            cp_commit();
            cp_wait<1>();
        } else {
            cp_wait<0>();
        }
        __syncthreads();

        const uint32_t kbase = sb + SKV_BASE + buf * SKV_STRIDE;

        float sacc[16][4];
#pragma unroll
        for (int i = 0; i < 16; i++)
#pragma unroll
            for (int t = 0; t < 4; t++) sacc[i][t] = 0.f;

#pragma unroll
        for (int kd = 0; kd < 8; kd++) {
            uint32_t aa = (uint32_t)((16 * wid + aRow) * QROWB + kd * 32 + aKof);
            uint32_t ah[4];
            ldm_x4(ah, sb + aa);
#pragma unroll
            for (int np = 0; np < 8; np++) {
                uint32_t ba = (uint32_t)((np * 16 + bRow) * KROWB + kd * 32 + bKof);
                uint32_t bh[4];
                ldm_x4(bh, kbase + OFF_KH + ba);
                mma16816(sacc[np * 2],     ah, bh[0], bh[1]);
                mma16816(sacc[np * 2 + 1], ah, bh[2], bh[3]);
            }
        }

        const int c0 = j * 128;
        if (j == nb - 1 && j == qb) {
#pragma unroll
            for (int ni = 0; ni < 16; ni++) {
                int cg = c0 + ni * 8 + 2 * tig;
                if (cg     > rg0) sacc[ni][0] = -1e30f;
                if (cg + 1 > rg0) sacc[ni][1] = -1e30f;
                if (cg     > rg1) sacc[ni][2] = -1e30f;
                if (cg + 1 > rg1) sacc[ni][3] = -1e30f;
            }
        }

        float vm0 = -1e30f, vm1 = -1e30f;
#pragma unroll
        for (int ni = 0; ni < 16; ni++) {
            vm0 = fmaxf(vm0, fmaxf(sacc[ni][0], sacc[ni][1]));
            vm1 = fmaxf(vm1, fmaxf(sacc[ni][2], sacc[ni][3]));
        }
        vm0 = fmaxf(vm0, __shfl_xor_sync(0xffffffffu, vm0, 1));
        vm0 = fmaxf(vm0, __shfl_xor_sync(0xffffffffu, vm0, 2));
        vm1 = fmaxf(vm1, __shfl_xor_sync(0xffffffffu, vm1, 1));
        vm1 = fmaxf(vm1, __shfl_xor_sync(0xffffffffu, vm1, 2));
        float mn0 = fmaxf(m0, vm0 * cs), mn1 = fmaxf(m1, vm1 * cs);
        float al0 = exp2f(m0 - mn0), al1 = exp2f(m1 - mn1);
        float sum0 = 0.f, sum1 = 0.f;
#pragma unroll
        for (int ni = 0; ni < 16; ni++) {
            sacc[ni][0] = exp2f(fmaf(sacc[ni][0], cs, -mn0));
            sacc[ni][1] = exp2f(fmaf(sacc[ni][1], cs, -mn0));
            sacc[ni][2] = exp2f(fmaf(sacc[ni][2], cs, -mn1));
            sacc[ni][3] = exp2f(fmaf(sacc[ni][3], cs, -mn1));
            sum0 += sacc[ni][0] + sacc[ni][1];
            sum1 += sacc[ni][2] + sacc[ni][3];
        }
        sum0 += __shfl_xor_sync(0xffffffffu, sum0, 1);
        sum0 += __shfl_xor_sync(0xffffffffu, sum0, 2);
        sum1 += __shfl_xor_sync(0xffffffffu, sum1, 1);
        sum1 += __shfl_xor_sync(0xffffffffu, sum1, 2);
        l0 = l0 * al0 + sum0;  l1 = l1 * al1 + sum1;
        m0 = mn0;  m1 = mn1;

#pragma unroll
        for (int nd = 0; nd < 16; nd++) {
            oacc[nd][0] *= al0;  oacc[nd][1] *= al0;
            oacc[nd][2] *= al1;  oacc[nd][3] *= al1;
        }

        uint32_t pah[8][4];
#pragma unroll
        for (int t = 0; t < 8; t++) {
            pah[t][0] = pack_h2(__float2half_rn(sacc[2 * t][0]),
                                __float2half_rn(sacc[2 * t][1]));
            pah[t][1] = pack_h2(__float2half_rn(sacc[2 * t][2]),
                                __float2half_rn(sacc[2 * t][3]));
            pah[t][2] = pack_h2(__float2half_rn(sacc[2 * t + 1][0]),
                                __float2half_rn(sacc[2 * t + 1][1]));
            pah[t][3] = pack_h2(__float2half_rn(sacc[2 * t + 1][2]),
                                __float2half_rn(sacc[2 * t + 1][3]));
        }

        // O += P @ V : B fragments from row-major V via ldmatrix.trans
#pragma unroll
        for (int t = 0; t < 8; t++) {
#pragma unroll
            for (int np = 0; np < 8; np++) {
                uint32_t ba = (uint32_t)((t * 16 + vRow) * VROWB + np * 32 + vKof);
                uint32_t vbh[4];
                ldm_x4_t(vbh, kbase + OFF_V + ba);
                mma16816(oacc[np * 2],     pah[t], vbh[0], vbh[1]);
                mma16816(oacc[np * 2 + 1], pah[t], vbh[2], vbh[3]);
            }
        }
        __syncthreads();
    }

    float inv0 = 1.f / l0, inv1 = 1.f / l1;
    size_t row0 = (size_t)(b * SEQ + qrow0 + 16 * wid + g) * HIDDEN + hq * HD;
    size_t row1 = row0 + (size_t)8 * HIDDEN;
#pragma unroll
    for (int nd = 0; nd < 16; nd++) {
        int col = nd * 8 + 2 * tig;
        *(uint32_t*)(aoh + row0 + col) = pack_h2(
            __float2half_rn(oacc[nd][0] * inv0), __float2half_rn(oacc[nd][1] * inv0));
        *(uint32_t*)(aoh + row1 + col) = pack_h2(
            __float2half_rn(oacc[nd][2] * inv1), __float2half_rn(oacc[nd][3] * inv1));
    }
}

// ============================================================================
extern "C" void kernel_launch(void* const* d_in, const int* in_sizes, int n_in,
                              void* d_out, int out_size)
{
    const float* x  = (const float*)d_in[0];
    const float* Wq = (const float*)d_in[1];
    const float* Wk = (const float*)d_in[2];
    const float* Wv = (const float*)d_in[3];
    const float* Wo = (const float*)d_in[4];
    float* out = (float*)d_out;

    __half *xh, *wqh, *wkh, *wvh, *woh;
    __half *qh, *kh, *vh, *aoh;
    cudaGetSymbolAddress((void**)&xh,  g_xh);
    cudaGetSymbolAddress((void**)&wqh, g_wqh);
    cudaGetSymbolAddress((void**)&wkh, g_wkh);
    cudaGetSymbolAddress((void**)&wvh, g_wvh);
    cudaGetSymbolAddress((void**)&woh, g_woh);
    cudaGetSymbolAddress((void**)&qh,  g_qh);
    cudaGetSymbolAddress((void**)&kh,  g_kh);
    cudaGetSymbolAddress((void**)&vh,  g_vh);
    cudaGetSymbolAddress((void**)&aoh, g_aoh);

    cudaFuncSetAttribute(qkv_hmma,   cudaFuncAttributeMaxDynamicSharedMemorySize, GEMM_SMEM);
    cudaFuncSetAttribute(gemm_wo,    cudaFuncAttributeMaxDynamicSharedMemorySize, GEMM_SMEM);
    cudaFuncSetAttribute(flash_hmma, cudaFuncAttributeMaxDynamicSharedMemorySize, FLASH_SMEM);

    split_all<<<(CVT_TOT + 255) / 256, 256>>>(
        (const float4*)x, (const float4*)Wq, (const float4*)Wk,
        (const float4*)Wv, (const float4*)Wo,
        (__half2*)xh, (__half2*)wqh, (__half2*)wkh, (__half2*)wvh, (__half2*)woh);

    qkv_hmma<<<dim3(6144 / BN, TOKENS / BM), 256, GEMM_SMEM>>>(
        xh, wqh, wkh, wvh, qh, kh, vh);

    flash_hmma<<<dim3(SEQ / 128, NH, BATCH), 256, FLASH_SMEM>>>(
        qh, kh, vh, aoh);

    gemm_wo<<<dim3(HIDDEN / BN, TOKENS / BM), 256, GEMM_SMEM>>>(
        aoh, woh, out, HIDDEN, HIDDEN);
}